// round 16
// baseline (speedup 1.0000x reference)
#include <cuda_runtime.h>
#include <math.h>
#include <float.h>

#define N_CAND 200000
#define DTXT 768
#define DIMG 1024
#define DC 256
#define KSEL 10
#define SIM_BLOCKS 148

// ---- device scratch (no allocations allowed) ----
__device__ float g_cv[SIM_BLOCKS * KSEL];
__device__ int   g_ci[SIM_BLOCKS * KSEL];
__device__ int   g_idx[KSEL];
__device__ float g_feats[21 * DC];
__device__ float g_qkv[23 * DC];
__device__ float g_out1[DC];
__device__ float g_h1[4 * DC];
__device__ float g_f[DC];
__device__ int   g_done2 = 0;
__device__ float g_dummy;

// ---- per-thread register top-10 insert (sorted desc) ----
// NOTE: compile-time register indexing ONLY (predicated unrolled loops);
// runtime indexing demotes to local memory (R13 lesson: +120us).
__device__ __forceinline__ void tk_insert_reg(float v, int i, float* tv, int* ti) {
    if (v > tv[KSEL - 1]) {
        int pos = 0;
#pragma unroll
        for (int j = 0; j < KSEL; j++) pos += (tv[j] >= v) ? 1 : 0;
#pragma unroll
        for (int j = KSEL - 2; j >= 0; j--) {
            if (j >= pos) { tv[j + 1] = tv[j]; ti[j + 1] = ti[j]; }
        }
#pragma unroll
        for (int j = 0; j < KSEL; j++) {
            if (j == pos) { tv[j] = v; ti[j] = i; }
        }
    }
}

// ============================================================
// 1) cosine-sim scan + fused per-block top-10 + tail weight
//    prefetch (warms L2 for the small kernels that follow).
//    148 blocks x 1024 = ONE wave, __ldcs streaming
// ============================================================
__global__ void __launch_bounds__(1024, 1) sim_kernel(
    const float* __restrict__ query, const float* __restrict__ cand,
    const float* __restrict__ W_txt, const float* __restrict__ W_img,
    const float* __restrict__ Wq, const float* __restrict__ Wk,
    const float* __restrict__ Wv, const float* __restrict__ Wo,
    const float* __restrict__ W1, const float* __restrict__ W2) {

    __shared__ float4 qs[DTXT / 4];
    __shared__ float wtv[32 * KSEL];
    __shared__ int   wti[32 * KSEL];
    int t = threadIdx.x, lane = t & 31, wid = t >> 5;

    for (int i = t; i < DTXT / 4; i += 1024) qs[i] = reinterpret_cast<const float4*>(query)[i];
    for (int i = t; i < 32 * KSEL; i += 1024) { wtv[i] = -FLT_MAX; wti[i] = -1; }
    __syncthreads();

    int gw = blockIdx.x * 32 + wid;
    int nw = SIM_BLOCKS * 32;
    float th = -FLT_MAX;

    for (int row = gw; row < N_CAND; row += nw) {
        const float4* rp = reinterpret_cast<const float4*>(cand + (size_t)row * DTXT);
        float4 c[6];
#pragma unroll
        for (int i = 0; i < 6; i++) c[i] = __ldcs(&rp[i * 32 + lane]);
        float dot = 0.f, ss = 0.f;
#pragma unroll
        for (int i = 0; i < 6; i++) {
            float4 q = qs[i * 32 + lane];
            dot += c[i].x * q.x + c[i].y * q.y + c[i].z * q.z + c[i].w * q.w;
            ss  += c[i].x * c[i].x + c[i].y * c[i].y + c[i].z * c[i].z + c[i].w * c[i].w;
        }
#pragma unroll
        for (int o = 16; o; o >>= 1) {
            dot += __shfl_xor_sync(0xffffffffu, dot, o);
            ss  += __shfl_xor_sync(0xffffffffu, ss,  o);
        }
        if (lane == 0) {
            float s = dot / fmaxf(sqrtf(ss), 1e-12f);
            if (s > th) {
                float* tv = &wtv[wid * KSEL]; int* ti = &wti[wid * KSEL];
                int pos = 0;
#pragma unroll
                for (int j = 0; j < KSEL; j++) pos += (tv[j] >= s) ? 1 : 0;
                for (int j = KSEL - 2; j >= pos; j--) { tv[j + 1] = tv[j]; ti[j + 1] = ti[j]; }
                tv[pos] = s; ti[pos] = row;
                th = tv[KSEL - 1];
            }
        }
    }
    __syncthreads();

    // warp 0: merge 32 sorted lists -> block top-10
    if (wid == 0) {
        int ptr = 0;
        for (int s = 0; s < KSEL; s++) {
            float v = (ptr < KSEL) ? wtv[lane * KSEL + ptr] : -FLT_MAX;
            float bv = v; int bl = lane;
#pragma unroll
            for (int o = 16; o; o >>= 1) {
                float ov = __shfl_xor_sync(0xffffffffu, bv, o);
                int   ol = __shfl_xor_sync(0xffffffffu, bl, o);
                if (ov > bv) { bv = ov; bl = ol; }
            }
            if (lane == bl) {
                g_cv[blockIdx.x * KSEL + s] = v;
                g_ci[blockIdx.x * KSEL + s] = wti[lane * KSEL + ptr];
                ptr++;
            }
        }
    }

    // ---- tail weight prefetch: warm L2 for the small kernels ----
    // Placed AFTER all scan work; <=2 float4 loads per thread (~4MB total,
    // ~0.6us of bandwidth spread over 151K threads). No merge logic here
    // (the R7/R8 in-kernel merge had the runtime-index local-mem bug).
    {
        float a = 0.f;
        unsigned g = blockIdx.x * 1024u + (unsigned)t;
        const unsigned stride = SIM_BLOCKS * 1024u;
        const float4* p;
        p = (const float4*)W_txt; for (unsigned i = g; i < 49152u; i += stride) { float4 v = __ldg(&p[i]); a += v.x; }
        p = (const float4*)W_img; for (unsigned i = g; i < 65536u; i += stride) { float4 v = __ldg(&p[i]); a += v.x; }
        p = (const float4*)Wq;    if (g < 16384u) { float4 v = __ldg(&p[g]); a += v.x; }
        p = (const float4*)Wk;    if (g < 16384u) { float4 v = __ldg(&p[g]); a += v.x; }
        p = (const float4*)Wv;    if (g < 16384u) { float4 v = __ldg(&p[g]); a += v.x; }
        p = (const float4*)Wo;    if (g < 16384u) { float4 v = __ldg(&p[g]); a += v.x; }
        p = (const float4*)W1;    for (unsigned i = g; i < 65536u; i += stride) { float4 v = __ldg(&p[i]); a += v.x; }
        p = (const float4*)W2;    for (unsigned i = g; i < 65536u; i += stride) { float4 v = __ldg(&p[i]); a += v.x; }
        if (a == 1.0e38f) g_dummy = a;   // never true; keeps loads live
    }
}

// ============================================================
// 2) top-10 final: reduce 1480 candidates -> g_idx (1 block)
// ============================================================
__global__ void topkB_kernel() {
    __shared__ float sv[256 * KSEL];
    __shared__ int   si[256 * KSEL];
    __shared__ float rv[256];
    __shared__ int   rj[256];
    int tid = threadIdx.x;

    float tv[KSEL]; int ti[KSEL];
#pragma unroll
    for (int j = 0; j < KSEL; j++) { tv[j] = -FLT_MAX; ti[j] = -1; }
    for (int i = tid; i < SIM_BLOCKS * KSEL; i += 256)
        tk_insert_reg(g_cv[i], g_ci[i], tv, ti);
#pragma unroll
    for (int j = 0; j < KSEL; j++) { sv[tid * KSEL + j] = tv[j]; si[tid * KSEL + j] = ti[j]; }
    __syncthreads();

    for (int s = 0; s < KSEL; s++) {
        float best = -FLT_MAX; int bj = tid * KSEL;
#pragma unroll
        for (int j = 0; j < KSEL; j++) {
            float v = sv[tid * KSEL + j];
            if (v > best) { best = v; bj = tid * KSEL + j; }
        }
        rv[tid] = best; rj[tid] = bj;
        __syncthreads();
        for (int off = 128; off; off >>= 1) {
            if (tid < off && rv[tid + off] > rv[tid]) { rv[tid] = rv[tid + off]; rj[tid] = rj[tid + off]; }
            __syncthreads();
        }
        if (tid == 0) { g_idx[s] = si[rj[0]]; sv[rj[0]] = -FLT_MAX; }
        __syncthreads();
    }
}

// ============================================================
// 3) proj + LN + ReLU fused, block-per-row, 21 blocks x 1024
// ============================================================
__global__ void __launch_bounds__(1024, 1) projln_kernel(
    const float* __restrict__ query,
    const float* __restrict__ cand_text,
    const float* __restrict__ cand_img,
    const float* __restrict__ W_txt, const float* __restrict__ b_txt,
    const float* __restrict__ g_txt, const float* __restrict__ be_txt,
    const float* __restrict__ W_img, const float* __restrict__ b_img,
    const float* __restrict__ g_img, const float* __restrict__ be_img) {

    __shared__ __align__(16) float xs[DIMG];
    __shared__ __align__(16) float zrow[DC];
    __shared__ float red[DC];
    int t = threadIdx.x, b = blockIdx.x;
    int lane = t & 31, w = t >> 5;

    const float* x; const float* W; const float* bb; int nf;
    const float* gg; const float* be;
    if (b == 0)      { x = query;                                     W = W_txt; bb = b_txt; nf = DTXT; gg = g_txt; be = be_txt; }
    else if (b <= 10){ x = cand_text + (size_t)g_idx[b - 1]  * DTXT;  W = W_txt; bb = b_txt; nf = DTXT; gg = g_txt; be = be_txt; }
    else             { x = cand_img  + (size_t)g_idx[b - 11] * DIMG;  W = W_img; bb = b_img; nf = DIMG; gg = g_img; be = be_img; }

    for (int i = t; i < nf; i += 1024) xs[i] = __ldg(&x[i]);
    __syncthreads();

    const float4* x4 = reinterpret_cast<const float4*>(xs);
    int nf4 = nf / 4;
#pragma unroll
    for (int j = 0; j < 8; j++) {
        int c = w * 8 + j;
        const float4* w4 = reinterpret_cast<const float4*>(W + (size_t)c * nf);
        float acc = 0.f;
        for (int i = 0; i < nf4 / 32; i++) {
            float4 a = x4[i * 32 + lane];
            float4 ww = __ldg(&w4[i * 32 + lane]);
            acc += a.x * ww.x + a.y * ww.y + a.z * ww.z + a.w * ww.w;
        }
#pragma unroll
        for (int o = 16; o; o >>= 1) acc += __shfl_xor_sync(0xffffffffu, acc, o);
        if (lane == 0) zrow[c] = acc + bb[c];
    }
    __syncthreads();

    if (t < DC) red[t] = zrow[t];
    __syncthreads();
    for (int off = 128; off; off >>= 1) { if (t < off) red[t] += red[t + off]; __syncthreads(); }
    float m = red[0] * (1.f / 256.f);
    __syncthreads();
    if (t < DC) { float d = zrow[t] - m; red[t] = d * d; }
    __syncthreads();
    for (int off = 128; off; off >>= 1) { if (t < off) red[t] += red[t + off]; __syncthreads(); }
    float var = red[0] * (1.f / 256.f);
    if (t < DC) {
        float y = (zrow[t] - m) * rsqrtf(var + 1e-5f) * gg[t] + be[t];
        g_feats[b * DC + t] = fmaxf(y, 0.f);
    }
}

// ============================================================
// 4) QKV matvecs: warp per output (23 rows x 256) -- wide
// ============================================================
__global__ void qkv_kernel(const float* __restrict__ proto,
                           const float* __restrict__ Wq, const float* __restrict__ bq,
                           const float* __restrict__ Wk, const float* __restrict__ bk,
                           const float* __restrict__ Wv, const float* __restrict__ bv) {
    int gw = (blockIdx.x * blockDim.x + threadIdx.x) >> 5;
    int lane = threadIdx.x & 31;
    int r = gw >> 8;
    int c = gw & 255;
    if (r >= 23) return;

    const float* x; const float* W; const float* b;
    if (r == 0)      { x = g_feats;                                    W = Wq; b = bq; }
    else if (r <= 11){ int n = r - 1;  x = (n == 0) ? proto : (g_feats + n * DC);        W = Wk; b = bk; }
    else             { int n = r - 12; x = (n == 0) ? proto : (g_feats + (10 + n) * DC); W = Wv; b = bv; }

    const float4* x4 = reinterpret_cast<const float4*>(x);
    const float4* w4 = reinterpret_cast<const float4*>(W + (size_t)c * DC);
    float acc = 0.f;
#pragma unroll
    for (int i = 0; i < 2; i++) {
        float4 a = __ldg(&x4[i * 32 + lane]);
        float4 w = __ldg(&w4[i * 32 + lane]);
        acc += a.x * w.x + a.y * w.y + a.z * w.z + a.w * w.w;
    }
#pragma unroll
    for (int o = 16; o; o >>= 1) acc += __shfl_xor_sync(0xffffffffu, acc, o);
    if (lane == 0) g_qkv[r * DC + c] = acc + b[c];
}

// ============================================================
// 5) attention + Wo + residual + LN1 (1 block x 1024)
// ============================================================
__global__ void __launch_bounds__(1024, 1) attn_kernel(const float* __restrict__ proto,
                            const float* __restrict__ Wo, const float* __restrict__ bo,
                            const float* __restrict__ g1, const float* __restrict__ be1) {
    __shared__ __align__(16) float qp[DC];
    __shared__ __align__(16) float kp[11 * DC];
    __shared__ __align__(16) float vp[11 * DC];
    __shared__ __align__(16) float at[48];
    __shared__ __align__(16) float ctx[DC];
    __shared__ __align__(16) float sy[DC];
    __shared__ float red[256];
    int t = threadIdx.x;
    int lane = t & 31, w = t >> 5;

    for (int i = t; i < DC; i += 1024) qp[i] = g_qkv[i];
    for (int i = t; i < 11 * DC; i += 1024) {
        kp[i] = g_qkv[DC + i];
        vp[i] = g_qkv[12 * DC + i];
    }
    __syncthreads();

    if (t < 44) {
        int h = t / 11, n = t % 11;
        float s = 0.f;
#pragma unroll
        for (int d = 0; d < 64; d++) s += qp[h * 64 + d] * kp[n * DC + h * 64 + d];
        at[t] = s * 0.125f;
    }
    __syncthreads();
    if (t < 4) {
        float mx = -FLT_MAX;
        for (int n = 0; n < 11; n++) mx = fmaxf(mx, at[t * 11 + n]);
        float sm = 0.f;
        for (int n = 0; n < 11; n++) { float e = expf(at[t * 11 + n] - mx); at[t * 11 + n] = e; sm += e; }
        float inv = 1.f / sm;
        for (int n = 0; n < 11; n++) at[t * 11 + n] *= inv;
    }
    __syncthreads();
    if (t < DC) {
        int h = t >> 6;
        float s = 0.f;
        for (int n = 0; n < 11; n++) s += at[h * 11 + n] * vp[n * DC + t];
        ctx[t] = s;
    }
    __syncthreads();

    const float4* c4 = reinterpret_cast<const float4*>(ctx);
#pragma unroll
    for (int j = 0; j < 8; j++) {
        int c = w * 8 + j;
        const float4* w4 = reinterpret_cast<const float4*>(Wo + (size_t)c * DC);
        float acc = 0.f;
#pragma unroll
        for (int i = 0; i < 2; i++) {
            float4 a = c4[i * 32 + lane];
            float4 ww = __ldg(&w4[i * 32 + lane]);
            acc += a.x * ww.x + a.y * ww.y + a.z * ww.z + a.w * ww.w;
        }
#pragma unroll
        for (int o = 16; o; o >>= 1) acc += __shfl_xor_sync(0xffffffffu, acc, o);
        if (lane == 0) sy[c] = acc + bo[c] + __ldg(&proto[c]);
    }
    __syncthreads();

    if (t < 256) red[t] = sy[t];
    __syncthreads();
    for (int off = 128; off; off >>= 1) { if (t < off) red[t] += red[t + off]; __syncthreads(); }
    float m = red[0] * (1.f / 256.f);
    __syncthreads();
    if (t < 256) { float dd = sy[t] - m; red[t] = dd * dd; }
    __syncthreads();
    for (int off = 128; off; off >>= 1) { if (t < off) red[t] += red[t + off]; __syncthreads(); }
    float var = red[0] * (1.f / 256.f);
    if (t < 256) g_out1[t] = (sy[t] - m) * rsqrtf(var + 1e-5f) * g1[t] + be1[t];
}

// ============================================================
// 6) FFN1: warp per output (1024 outputs, dot-256), 32 x 1024
// ============================================================
__global__ void __launch_bounds__(1024, 1) ffn1_kernel(const float* __restrict__ W1,
                                                       const float* __restrict__ b1) {
    int gw = (blockIdx.x * blockDim.x + threadIdx.x) >> 5;
    int lane = threadIdx.x & 31;
    const float4* x4 = reinterpret_cast<const float4*>(g_out1);
    const float4* w4 = reinterpret_cast<const float4*>(W1 + (size_t)gw * DC);
    float acc = 0.f;
#pragma unroll
    for (int i = 0; i < 2; i++) {
        float4 a = __ldg(&x4[i * 32 + lane]);
        float4 w = __ldg(&w4[i * 32 + lane]);
        acc += a.x * w.x + a.y * w.y + a.z * w.z + a.w * w.w;
    }
#pragma unroll
    for (int o = 16; o; o >>= 1) acc += __shfl_xor_sync(0xffffffffu, acc, o);
    if (lane == 0) g_h1[gw] = fmaxf(acc + b1[gw], 0.f);
}

// ============================================================
// 7) FFN2 + fused final LN2 (last block): 8 x 1024
// ============================================================
__global__ void __launch_bounds__(1024, 1) ffn2_kernel(const float* __restrict__ W2,
                                                       const float* __restrict__ b2,
                                                       const float* __restrict__ proto,
                                                       const float* __restrict__ g2,
                                                       const float* __restrict__ be2,
                                                       float* __restrict__ out) {
    __shared__ int sdone;
    int t = threadIdx.x, lane = t & 31, w = t >> 5;
    int c = blockIdx.x * 32 + w;

    const float4* x4 = reinterpret_cast<const float4*>(g_h1);
    const float4* w4 = reinterpret_cast<const float4*>(W2 + (size_t)c * (4 * DC));
    float acc = 0.f;
#pragma unroll
    for (int i = 0; i < 8; i++) {
        float4 a = __ldg(&x4[i * 32 + lane]);
        float4 ww = __ldg(&w4[i * 32 + lane]);
        acc += a.x * ww.x + a.y * ww.y + a.z * ww.z + a.w * ww.w;
    }
#pragma unroll
    for (int o = 16; o; o >>= 1) acc += __shfl_xor_sync(0xffffffffu, acc, o);
    if (lane == 0) g_f[c] = acc + b2[c];

    __syncthreads();
    if (t == 0) {
        __threadfence();
        sdone = (atomicAdd(&g_done2, 1) == 7) ? 1 : 0;
    }
    __syncthreads();
    if (sdone) {
        __threadfence();
        if (w == 0) {
            float e[8];
#pragma unroll
            for (int j = 0; j < 8; j++) {
                int cc = lane + 32 * j;
                e[j] = g_f[cc] + g_out1[cc];
            }
            float sm = 0.f;
#pragma unroll
            for (int j = 0; j < 8; j++) sm += e[j];
#pragma unroll
            for (int o = 16; o; o >>= 1) sm += __shfl_xor_sync(0xffffffffu, sm, o);
            float m = sm * (1.f / 256.f);
            float vv = 0.f;
#pragma unroll
            for (int j = 0; j < 8; j++) { float d = e[j] - m; vv += d * d; }
#pragma unroll
            for (int o = 16; o; o >>= 1) vv += __shfl_xor_sync(0xffffffffu, vv, o);
            float rstd = rsqrtf(vv * (1.f / 256.f) + 1e-5f);
#pragma unroll
            for (int j = 0; j < 8; j++) {
                int cc = lane + 32 * j;
                out[cc] = (e[j] - m) * rstd * __ldg(&g2[cc]) + __ldg(&be2[cc]) + __ldg(&proto[cc]);
            }
        }
        if (t == 0) g_done2 = 0;
    }
}

// ============================================================
extern "C" void kernel_launch(void* const* d_in, const int* in_sizes, int n_in,
                              void* d_out, int out_size) {
    const float* query     = (const float*)d_in[0];
    const float* cand_text = (const float*)d_in[1];
    const float* cand_img  = (const float*)d_in[2];
    const float* proto     = (const float*)d_in[3];
    const float* W_txt  = (const float*)d_in[4];
    const float* b_txt  = (const float*)d_in[5];
    const float* g_txt  = (const float*)d_in[6];
    const float* be_txt = (const float*)d_in[7];
    const float* W_img  = (const float*)d_in[8];
    const float* b_img  = (const float*)d_in[9];
    const float* g_img  = (const float*)d_in[10];
    const float* be_img = (const float*)d_in[11];
    const float* Wq = (const float*)d_in[12];
    const float* bq = (const float*)d_in[13];
    const float* Wk = (const float*)d_in[14];
    const float* bk = (const float*)d_in[15];
    const float* Wv = (const float*)d_in[16];
    const float* bv = (const float*)d_in[17];
    const float* Wo = (const float*)d_in[18];
    const float* bo = (const float*)d_in[19];
    const float* g1  = (const float*)d_in[20];
    const float* be1 = (const float*)d_in[21];
    const float* W1 = (const float*)d_in[22];
    const float* b1 = (const float*)d_in[23];
    const float* W2 = (const float*)d_in[24];
    const float* b2 = (const float*)d_in[25];
    const float* g2  = (const float*)d_in[26];
    const float* be2 = (const float*)d_in[27];
    float* out = (float*)d_out;

    sim_kernel<<<SIM_BLOCKS, 1024>>>(query, cand_text, W_txt, W_img,
                                     Wq, Wk, Wv, Wo, W1, W2);
    topkB_kernel<<<1, 256>>>();
    projln_kernel<<<21, 1024>>>(query, cand_text, cand_img,
                                W_txt, b_txt, g_txt, be_txt,
                                W_img, b_img, g_img, be_img);
    qkv_kernel<<<736, 256>>>(proto, Wq, bq, Wk, bk, Wv, bv);
    attn_kernel<<<1, 1024>>>(proto, Wo, bo, g1, be1);
    ffn1_kernel<<<32, 1024>>>(W1, b1);
    ffn2_kernel<<<8, 1024>>>(W2, b2, proto, g2, be2, out);
}

// round 17
// speedup vs baseline: 1.0312x; 1.0312x over previous
#include <cuda_runtime.h>
#include <math.h>
#include <float.h>

#define N_CAND 200000
#define DTXT 768
#define DIMG 1024
#define DC 256
#define KSEL 10
#define SIM_BLOCKS 148

// ---- device scratch (no allocations allowed) ----
__device__ float g_cv[SIM_BLOCKS * KSEL];
__device__ int   g_ci[SIM_BLOCKS * KSEL];
__device__ int   g_idx[KSEL];
__device__ float g_feats[21 * DC];
__device__ float g_qkv[23 * DC];
__device__ float g_sy[DC];
__device__ float g_out1[DC];
__device__ float g_h1[4 * DC];
__device__ float g_f[DC];
__device__ int   g_done1 = 0;
__device__ int   g_done2 = 0;

// ---- per-thread register top-10 insert (sorted desc) ----
// NOTE: compile-time register indexing ONLY (predicated unrolled loops);
// runtime indexing demotes to local memory (R13 lesson: +120us).
__device__ __forceinline__ void tk_insert_reg(float v, int i, float* tv, int* ti) {
    if (v > tv[KSEL - 1]) {
        int pos = 0;
#pragma unroll
        for (int j = 0; j < KSEL; j++) pos += (tv[j] >= v) ? 1 : 0;
#pragma unroll
        for (int j = KSEL - 2; j >= 0; j--) {
            if (j >= pos) { tv[j + 1] = tv[j]; ti[j + 1] = ti[j]; }
        }
#pragma unroll
        for (int j = 0; j < KSEL; j++) {
            if (j == pos) { tv[j] = v; ti[j] = i; }
        }
    }
}

// ============================================================
// 1) cosine-sim scan + fused per-block top-10
//    148 blocks x 1024 = ONE wave, __ldcs streaming
// ============================================================
__global__ void __launch_bounds__(1024, 1) sim_kernel(const float* __restrict__ query,
                                                      const float* __restrict__ cand) {
    __shared__ float4 qs[DTXT / 4];
    __shared__ float wtv[32 * KSEL];
    __shared__ int   wti[32 * KSEL];
    int t = threadIdx.x, lane = t & 31, wid = t >> 5;

    for (int i = t; i < DTXT / 4; i += 1024) qs[i] = reinterpret_cast<const float4*>(query)[i];
    for (int i = t; i < 32 * KSEL; i += 1024) { wtv[i] = -FLT_MAX; wti[i] = -1; }
    __syncthreads();

    int gw = blockIdx.x * 32 + wid;
    int nw = SIM_BLOCKS * 32;
    float th = -FLT_MAX;

    for (int row = gw; row < N_CAND; row += nw) {
        const float4* rp = reinterpret_cast<const float4*>(cand + (size_t)row * DTXT);
        float4 c[6];
#pragma unroll
        for (int i = 0; i < 6; i++) c[i] = __ldcs(&rp[i * 32 + lane]);
        float dot = 0.f, ss = 0.f;
#pragma unroll
        for (int i = 0; i < 6; i++) {
            float4 q = qs[i * 32 + lane];
            dot += c[i].x * q.x + c[i].y * q.y + c[i].z * q.z + c[i].w * q.w;
            ss  += c[i].x * c[i].x + c[i].y * c[i].y + c[i].z * c[i].z + c[i].w * c[i].w;
        }
#pragma unroll
        for (int o = 16; o; o >>= 1) {
            dot += __shfl_xor_sync(0xffffffffu, dot, o);
            ss  += __shfl_xor_sync(0xffffffffu, ss,  o);
        }
        if (lane == 0) {
            float s = dot / fmaxf(sqrtf(ss), 1e-12f);
            if (s > th) {
                float* tv = &wtv[wid * KSEL]; int* ti = &wti[wid * KSEL];
                int pos = 0;
#pragma unroll
                for (int j = 0; j < KSEL; j++) pos += (tv[j] >= s) ? 1 : 0;
                for (int j = KSEL - 2; j >= pos; j--) { tv[j + 1] = tv[j]; ti[j + 1] = ti[j]; }
                tv[pos] = s; ti[pos] = row;
                th = tv[KSEL - 1];
            }
        }
    }
    __syncthreads();

    // warp 0: merge 32 sorted lists -> block top-10
    if (wid == 0) {
        int ptr = 0;
        for (int s = 0; s < KSEL; s++) {
            float v = (ptr < KSEL) ? wtv[lane * KSEL + ptr] : -FLT_MAX;
            float bv = v; int bl = lane;
#pragma unroll
            for (int o = 16; o; o >>= 1) {
                float ov = __shfl_xor_sync(0xffffffffu, bv, o);
                int   ol = __shfl_xor_sync(0xffffffffu, bl, o);
                if (ov > bv) { bv = ov; bl = ol; }
            }
            if (lane == bl) {
                g_cv[blockIdx.x * KSEL + s] = v;
                g_ci[blockIdx.x * KSEL + s] = wti[lane * KSEL + ptr];
                ptr++;
            }
        }
    }
}

// ============================================================
// 2) top-10 final: reduce 1480 candidates -> g_idx (1 block)
// ============================================================
__global__ void topkB_kernel() {
    __shared__ float sv[256 * KSEL];
    __shared__ int   si[256 * KSEL];
    __shared__ float rv[256];
    __shared__ int   rj[256];
    int tid = threadIdx.x;

    float tv[KSEL]; int ti[KSEL];
#pragma unroll
    for (int j = 0; j < KSEL; j++) { tv[j] = -FLT_MAX; ti[j] = -1; }
    for (int i = tid; i < SIM_BLOCKS * KSEL; i += 256)
        tk_insert_reg(g_cv[i], g_ci[i], tv, ti);
#pragma unroll
    for (int j = 0; j < KSEL; j++) { sv[tid * KSEL + j] = tv[j]; si[tid * KSEL + j] = ti[j]; }
    __syncthreads();

    for (int s = 0; s < KSEL; s++) {
        float best = -FLT_MAX; int bj = tid * KSEL;
#pragma unroll
        for (int j = 0; j < KSEL; j++) {
            float v = sv[tid * KSEL + j];
            if (v > best) { best = v; bj = tid * KSEL + j; }
        }
        rv[tid] = best; rj[tid] = bj;
        __syncthreads();
        for (int off = 128; off; off >>= 1) {
            if (tid < off && rv[tid + off] > rv[tid]) { rv[tid] = rv[tid + off]; rj[tid] = rj[tid + off]; }
            __syncthreads();
        }
        if (tid == 0) { g_idx[s] = si[rj[0]]; sv[rj[0]] = -FLT_MAX; }
        __syncthreads();
    }
}

// ============================================================
// 3) proj + LN + ReLU fused, block-per-row, 21 blocks x 1024
// ============================================================
__global__ void __launch_bounds__(1024, 1) projln_kernel(
    const float* __restrict__ query,
    const float* __restrict__ cand_text,
    const float* __restrict__ cand_img,
    const float* __restrict__ W_txt, const float* __restrict__ b_txt,
    const float* __restrict__ g_txt, const float* __restrict__ be_txt,
    const float* __restrict__ W_img, const float* __restrict__ b_img,
    const float* __restrict__ g_img, const float* __restrict__ be_img) {

    __shared__ __align__(16) float xs[DIMG];
    __shared__ __align__(16) float zrow[DC];
    __shared__ float red[DC];
    int t = threadIdx.x, b = blockIdx.x;
    int lane = t & 31, w = t >> 5;

    const float* x; const float* W; const float* bb; int nf;
    const float* gg; const float* be;
    if (b == 0)      { x = query;                                     W = W_txt; bb = b_txt; nf = DTXT; gg = g_txt; be = be_txt; }
    else if (b <= 10){ x = cand_text + (size_t)g_idx[b - 1]  * DTXT;  W = W_txt; bb = b_txt; nf = DTXT; gg = g_txt; be = be_txt; }
    else             { x = cand_img  + (size_t)g_idx[b - 11] * DIMG;  W = W_img; bb = b_img; nf = DIMG; gg = g_img; be = be_img; }

    for (int i = t; i < nf; i += 1024) xs[i] = __ldg(&x[i]);
    __syncthreads();

    const float4* x4 = reinterpret_cast<const float4*>(xs);
    int nf4 = nf / 4;
#pragma unroll
    for (int j = 0; j < 8; j++) {
        int c = w * 8 + j;
        const float4* w4 = reinterpret_cast<const float4*>(W + (size_t)c * nf);
        float acc = 0.f;
        for (int i = 0; i < nf4 / 32; i++) {
            float4 a = x4[i * 32 + lane];
            float4 ww = __ldg(&w4[i * 32 + lane]);
            acc += a.x * ww.x + a.y * ww.y + a.z * ww.z + a.w * ww.w;
        }
#pragma unroll
        for (int o = 16; o; o >>= 1) acc += __shfl_xor_sync(0xffffffffu, acc, o);
        if (lane == 0) zrow[c] = acc + bb[c];
    }
    __syncthreads();

    if (t < DC) red[t] = zrow[t];
    __syncthreads();
    for (int off = 128; off; off >>= 1) { if (t < off) red[t] += red[t + off]; __syncthreads(); }
    float m = red[0] * (1.f / 256.f);
    __syncthreads();
    if (t < DC) { float d = zrow[t] - m; red[t] = d * d; }
    __syncthreads();
    for (int off = 128; off; off >>= 1) { if (t < off) red[t] += red[t + off]; __syncthreads(); }
    float var = red[0] * (1.f / 256.f);
    if (t < DC) {
        float y = (zrow[t] - m) * rsqrtf(var + 1e-5f) * gg[t] + be[t];
        g_feats[b * DC + t] = fmaxf(y, 0.f);
    }
}

// ============================================================
// 4) QKV matvecs: warp per output (23 rows x 256) -- wide
// ============================================================
__global__ void qkv_kernel(const float* __restrict__ proto,
                           const float* __restrict__ Wq, const float* __restrict__ bq,
                           const float* __restrict__ Wk, const float* __restrict__ bk,
                           const float* __restrict__ Wv, const float* __restrict__ bv) {
    int gw = (blockIdx.x * blockDim.x + threadIdx.x) >> 5;
    int lane = threadIdx.x & 31;
    int r = gw >> 8;
    int c = gw & 255;
    if (r >= 23) return;

    const float* x; const float* W; const float* b;
    if (r == 0)      { x = g_feats;                                    W = Wq; b = bq; }
    else if (r <= 11){ int n = r - 1;  x = (n == 0) ? proto : (g_feats + n * DC);        W = Wk; b = bk; }
    else             { int n = r - 12; x = (n == 0) ? proto : (g_feats + (10 + n) * DC); W = Wv; b = bv; }

    const float4* x4 = reinterpret_cast<const float4*>(x);
    const float4* w4 = reinterpret_cast<const float4*>(W + (size_t)c * DC);
    float acc = 0.f;
#pragma unroll
    for (int i = 0; i < 2; i++) {
        float4 a = __ldg(&x4[i * 32 + lane]);
        float4 w = __ldg(&w4[i * 32 + lane]);
        acc += a.x * w.x + a.y * w.y + a.z * w.z + a.w * w.w;
    }
#pragma unroll
    for (int o = 16; o; o >>= 1) acc += __shfl_xor_sync(0xffffffffu, acc, o);
    if (lane == 0) g_qkv[r * DC + c] = acc + b[c];
}

// ============================================================
// 5) attention WIDE: 8 blocks x 1024. Each block redundantly
//    computes scores/softmax/ctx (cheap, L2-hot qkv), then owns
//    32 Wo output columns. Last block (atomic gate) runs LN1.
// ============================================================
__global__ void __launch_bounds__(1024, 1) attn_kernel(const float* __restrict__ proto,
                            const float* __restrict__ Wo, const float* __restrict__ bo,
                            const float* __restrict__ g1, const float* __restrict__ be1) {
    __shared__ __align__(16) float qp[DC];
    __shared__ __align__(16) float kp[11 * DC];
    __shared__ __align__(16) float vp[11 * DC];
    __shared__ __align__(16) float at[48];
    __shared__ __align__(16) float ctx[DC];
    __shared__ int sdone;
    int t = threadIdx.x, b = blockIdx.x;
    int lane = t & 31, w = t >> 5;

    for (int i = t; i < DC; i += 1024) qp[i] = g_qkv[i];
    for (int i = t; i < 11 * DC; i += 1024) {
        kp[i] = g_qkv[DC + i];
        vp[i] = g_qkv[12 * DC + i];
    }
    __syncthreads();

    if (t < 44) {
        int h = t / 11, n = t % 11;
        float s = 0.f;
#pragma unroll
        for (int d = 0; d < 64; d++) s += qp[h * 64 + d] * kp[n * DC + h * 64 + d];
        at[t] = s * 0.125f;
    }
    __syncthreads();
    if (t < 4) {
        float mx = -FLT_MAX;
        for (int n = 0; n < 11; n++) mx = fmaxf(mx, at[t * 11 + n]);
        float sm = 0.f;
        for (int n = 0; n < 11; n++) { float e = expf(at[t * 11 + n] - mx); at[t * 11 + n] = e; sm += e; }
        float inv = 1.f / sm;
        for (int n = 0; n < 11; n++) at[t * 11 + n] *= inv;
    }
    __syncthreads();
    if (t < DC) {
        int h = t >> 6;
        float s = 0.f;
        for (int n = 0; n < 11; n++) s += at[h * 11 + n] * vp[n * DC + t];
        ctx[t] = s;
    }
    __syncthreads();

    // Wo slice: block b owns columns [b*32, b*32+32), warp per output
    {
        int c = b * 32 + w;
        const float4* c4 = reinterpret_cast<const float4*>(ctx);
        const float4* w4 = reinterpret_cast<const float4*>(Wo + (size_t)c * DC);
        float acc = 0.f;
#pragma unroll
        for (int i = 0; i < 2; i++) {
            float4 a = c4[i * 32 + lane];
            float4 ww = __ldg(&w4[i * 32 + lane]);
            acc += a.x * ww.x + a.y * ww.y + a.z * ww.z + a.w * ww.w;
        }
#pragma unroll
        for (int o = 16; o; o >>= 1) acc += __shfl_xor_sync(0xffffffffu, acc, o);
        if (lane == 0) g_sy[c] = acc + bo[c] + __ldg(&proto[c]);
    }

    // gate: last block to finish runs LN1 -> g_out1
    __syncthreads();
    if (t == 0) {
        __threadfence();
        sdone = (atomicAdd(&g_done1, 1) == gridDim.x - 1) ? 1 : 0;
    }
    __syncthreads();
    if (!sdone) return;
    __threadfence();

    if (w == 0) {
        float e[8];
#pragma unroll
        for (int j = 0; j < 8; j++) e[j] = g_sy[lane + 32 * j];
        float sm = 0.f;
#pragma unroll
        for (int j = 0; j < 8; j++) sm += e[j];
#pragma unroll
        for (int o = 16; o; o >>= 1) sm += __shfl_xor_sync(0xffffffffu, sm, o);
        float m = sm * (1.f / 256.f);
        float vv = 0.f;
#pragma unroll
        for (int j = 0; j < 8; j++) { float d = e[j] - m; vv += d * d; }
#pragma unroll
        for (int o = 16; o; o >>= 1) vv += __shfl_xor_sync(0xffffffffu, vv, o);
        float rstd = rsqrtf(vv * (1.f / 256.f) + 1e-5f);
#pragma unroll
        for (int j = 0; j < 8; j++) {
            int cc = lane + 32 * j;
            g_out1[cc] = (e[j] - m) * rstd * __ldg(&g1[cc]) + __ldg(&be1[cc]);
        }
    }
    if (t == 0) g_done1 = 0;   // reset for next graph replay
}

// ============================================================
// 6) FFN1: warp per output (1024 outputs, dot-256), 32 x 1024
// ============================================================
__global__ void __launch_bounds__(1024, 1) ffn1_kernel(const float* __restrict__ W1,
                                                       const float* __restrict__ b1) {
    int gw = (blockIdx.x * blockDim.x + threadIdx.x) >> 5;
    int lane = threadIdx.x & 31;
    const float4* x4 = reinterpret_cast<const float4*>(g_out1);
    const float4* w4 = reinterpret_cast<const float4*>(W1 + (size_t)gw * DC);
    float acc = 0.f;
#pragma unroll
    for (int i = 0; i < 2; i++) {
        float4 a = __ldg(&x4[i * 32 + lane]);
        float4 w = __ldg(&w4[i * 32 + lane]);
        acc += a.x * w.x + a.y * w.y + a.z * w.z + a.w * w.w;
    }
#pragma unroll
    for (int o = 16; o; o >>= 1) acc += __shfl_xor_sync(0xffffffffu, acc, o);
    if (lane == 0) g_h1[gw] = fmaxf(acc + b1[gw], 0.f);
}

// ============================================================
// 7) FFN2 + fused final LN2 (last block): 8 x 1024
// ============================================================
__global__ void __launch_bounds__(1024, 1) ffn2_kernel(const float* __restrict__ W2,
                                                       const float* __restrict__ b2,
                                                       const float* __restrict__ proto,
                                                       const float* __restrict__ g2,
                                                       const float* __restrict__ be2,
                                                       float* __restrict__ out) {
    __shared__ int sdone;
    int t = threadIdx.x, lane = t & 31, w = t >> 5;
    int c = blockIdx.x * 32 + w;

    const float4* x4 = reinterpret_cast<const float4*>(g_h1);
    const float4* w4 = reinterpret_cast<const float4*>(W2 + (size_t)c * (4 * DC));
    float acc = 0.f;
#pragma unroll
    for (int i = 0; i < 8; i++) {
        float4 a = __ldg(&x4[i * 32 + lane]);
        float4 ww = __ldg(&w4[i * 32 + lane]);
        acc += a.x * ww.x + a.y * ww.y + a.z * ww.z + a.w * ww.w;
    }
#pragma unroll
    for (int o = 16; o; o >>= 1) acc += __shfl_xor_sync(0xffffffffu, acc, o);
    if (lane == 0) g_f[c] = acc + b2[c];

    __syncthreads();
    if (t == 0) {
        __threadfence();
        sdone = (atomicAdd(&g_done2, 1) == 7) ? 1 : 0;
    }
    __syncthreads();
    if (sdone) {
        __threadfence();
        if (w == 0) {
            float e[8];
#pragma unroll
            for (int j = 0; j < 8; j++) {
                int cc = lane + 32 * j;
                e[j] = g_f[cc] + g_out1[cc];
            }
            float sm = 0.f;
#pragma unroll
            for (int j = 0; j < 8; j++) sm += e[j];
#pragma unroll
            for (int o = 16; o; o >>= 1) sm += __shfl_xor_sync(0xffffffffu, sm, o);
            float m = sm * (1.f / 256.f);
            float vv = 0.f;
#pragma unroll
            for (int j = 0; j < 8; j++) { float d = e[j] - m; vv += d * d; }
#pragma unroll
            for (int o = 16; o; o >>= 1) vv += __shfl_xor_sync(0xffffffffu, vv, o);
            float rstd = rsqrtf(vv * (1.f / 256.f) + 1e-5f);
#pragma unroll
            for (int j = 0; j < 8; j++) {
                int cc = lane + 32 * j;
                out[cc] = (e[j] - m) * rstd * __ldg(&g2[cc]) + __ldg(&be2[cc]) + __ldg(&proto[cc]);
            }
        }
        if (t == 0) g_done2 = 0;
    }
}

// ============================================================
extern "C" void kernel_launch(void* const* d_in, const int* in_sizes, int n_in,
                              void* d_out, int out_size) {
    const float* query     = (const float*)d_in[0];
    const float* cand_text = (const float*)d_in[1];
    const float* cand_img  = (const float*)d_in[2];
    const float* proto     = (const float*)d_in[3];
    const float* W_txt  = (const float*)d_in[4];
    const float* b_txt  = (const float*)d_in[5];
    const float* g_txt  = (const float*)d_in[6];
    const float* be_txt = (const float*)d_in[7];
    const float* W_img  = (const float*)d_in[8];
    const float* b_img  = (const float*)d_in[9];
    const float* g_img  = (const float*)d_in[10];
    const float* be_img = (const float*)d_in[11];
    const float* Wq = (const float*)d_in[12];
    const float* bq = (const float*)d_in[13];
    const float* Wk = (const float*)d_in[14];
    const float* bk = (const float*)d_in[15];
    const float* Wv = (const float*)d_in[16];
    const float* bv = (const float*)d_in[17];
    const float* Wo = (const float*)d_in[18];
    const float* bo = (const float*)d_in[19];
    const float* g1  = (const float*)d_in[20];
    const float* be1 = (const float*)d_in[21];
    const float* W1 = (const float*)d_in[22];
    const float* b1 = (const float*)d_in[23];
    const float* W2 = (const float*)d_in[24];
    const float* b2 = (const float*)d_in[25];
    const float* g2  = (const float*)d_in[26];
    const float* be2 = (const float*)d_in[27];
    float* out = (float*)d_out;

    sim_kernel<<<SIM_BLOCKS, 1024>>>(query, cand_text);
    topkB_kernel<<<1, 256>>>();
    projln_kernel<<<21, 1024>>>(query, cand_text, cand_img,
                                W_txt, b_txt, g_txt, be_txt,
                                W_img, b_img, g_img, be_img);
    qkv_kernel<<<736, 256>>>(proto, Wq, bq, Wk, bk, Wv, bv);
    attn_kernel<<<8, 1024>>>(proto, Wo, bo, g1, be1);
    ffn1_kernel<<<32, 1024>>>(W1, b1);
    ffn2_kernel<<<8, 1024>>>(W2, b2, proto, g2, be2, out);
}